// round 1
// baseline (speedup 1.0000x reference)
#include <cuda_runtime.h>

// S2Conv: channel-shifted signal -> cross-channel depthwise conv (window 9)
// -> per-channel batchnorm over (N,T) -> gamma/beta -> relu.
// N=64, C=128, T=2048, S=9, D=1.

#define Nn 64
#define Cc 128
#define Tt 2048
#define Ss 9
#define TB 128   // time tile
#define CG 16    // channel group per block

__device__ float g_sum[Cc];
__device__ float g_sumsq[Cc];
__device__ float g_scale[Cc];
__device__ float g_bias[Cc];

__global__ void zero_kernel() {
    int i = threadIdx.x;
    if (i < Cc) { g_sum[i] = 0.0f; g_sumsq[i] = 0.0f; }
}

// Pass 1: conv + per-channel partial stats.
// Block: one n, CG output channels, TB times. 256 threads.
__global__ __launch_bounds__(256) void conv_stats_kernel(
    const float* __restrict__ x,
    const float* __restrict__ w,
    float* __restrict__ out)
{
    __shared__ float tile[CG + 8][TB];   // pre-shifted xs, 24 x 128
    __shared__ float s_w[CG][Ss];
    __shared__ float s_sum[CG], s_sq[CG];

    const int t0  = blockIdx.x * TB;
    const int cg0 = blockIdx.y * CG;
    const int n   = blockIdx.z;
    const int tid = threadIdx.x;

    if (tid < CG * Ss) {
        int cl = tid / Ss, s = tid % Ss;
        s_w[cl][s] = w[(cg0 + cl) * Ss + s];
    }
    if (tid < CG) { s_sum[tid] = 0.0f; s_sq[tid] = 0.0f; }

    // Load channel-shifted tile: tile[lc][j] = xs[n, cg0-4+lc, t0+j]
    // where xs[n,cc,t] = x[n,cc,t + (4 - cc%9)] with zero padding.
    const float* xn = x + (size_t)n * Cc * Tt;
    #pragma unroll 4
    for (int i = tid; i < (CG + 8) * TB; i += 256) {
        int lc = i >> 7;           // / TB
        int j  = i & (TB - 1);
        int cc = cg0 - 4 + lc;
        float v = 0.0f;
        if (cc >= 0 && cc < Cc) {
            int off = 4 - (cc % 9);
            int ts  = t0 + j + off;
            if (ts >= 0 && ts < Tt) v = xn[cc * Tt + ts];
        }
        tile[lc][j] = v;
    }
    __syncthreads();

    const int j    = tid & (TB - 1);
    const int half = tid >> 7;     // 0 or 1
    float* outn = out + (size_t)n * Cc * Tt;

    for (int cl = half; cl < CG; cl += 2) {
        float acc = 0.0f;
        #pragma unroll
        for (int s = 0; s < Ss; s++)
            acc = fmaf(s_w[cl][s], tile[cl + s][j], acc);
        outn[(size_t)(cg0 + cl) * Tt + t0 + j] = acc;

        float a = acc, q = acc * acc;
        #pragma unroll
        for (int o = 16; o > 0; o >>= 1) {
            a += __shfl_down_sync(0xffffffffu, a, o);
            q += __shfl_down_sync(0xffffffffu, q, o);
        }
        if ((tid & 31) == 0) {
            atomicAdd(&s_sum[cl], a);
            atomicAdd(&s_sq[cl], q);
        }
    }
    __syncthreads();
    if (tid < CG) {
        atomicAdd(&g_sum[cg0 + tid],   s_sum[tid]);
        atomicAdd(&g_sumsq[cg0 + tid], s_sq[tid]);
    }
}

// Pass 2: fold stats + gamma/beta into per-channel scale/bias.
__global__ void finalize_kernel(const float* __restrict__ gamma,
                                const float* __restrict__ beta)
{
    int c = threadIdx.x;
    if (c >= Cc) return;
    const float inv = 1.0f / ((float)Nn * (float)Tt);
    float mean = g_sum[c] * inv;
    float var  = g_sumsq[c] * inv - mean * mean;
    float rstd = rsqrtf(var + 1e-5f);
    float sc   = gamma[c] * rstd;
    g_scale[c] = sc;
    g_bias[c]  = beta[c] - mean * sc;
}

// Pass 3: in-place normalize + relu. One block per (n,c) row, float4.
__global__ __launch_bounds__(256) void norm_kernel(float* __restrict__ out)
{
    const int row = blockIdx.x;          // n*C + c
    const int c   = row & (Cc - 1);
    const float sc = g_scale[c];
    const float b  = g_bias[c];
    float4* p = reinterpret_cast<float4*>(out + (size_t)row * Tt);
    const int tid = threadIdx.x;
    #pragma unroll
    for (int k = 0; k < (Tt / 4) / 256; k++) {
        float4 v = p[tid + k * 256];
        v.x = fmaxf(fmaf(v.x, sc, b), 0.0f);
        v.y = fmaxf(fmaf(v.y, sc, b), 0.0f);
        v.z = fmaxf(fmaf(v.z, sc, b), 0.0f);
        v.w = fmaxf(fmaf(v.w, sc, b), 0.0f);
        p[tid + k * 256] = v;
    }
}

extern "C" void kernel_launch(void* const* d_in, const int* in_sizes, int n_in,
                              void* d_out, int out_size)
{
    const float* x     = (const float*)d_in[0];
    const float* w     = (const float*)d_in[1];
    const float* gamma = (const float*)d_in[2];
    const float* beta  = (const float*)d_in[3];
    float* out = (float*)d_out;

    zero_kernel<<<1, 128>>>();
    conv_stats_kernel<<<dim3(Tt / TB, Cc / CG, Nn), 256>>>(x, w, out);
    finalize_kernel<<<1, 128>>>(gamma, beta);
    norm_kernel<<<Nn * Cc, 256>>>(out);
}